// round 3
// baseline (speedup 1.0000x reference)
#include <cuda_runtime.h>
#include <math.h>

#define BATCH 4
#define CH    512
#define HW    4096
#define NG    32

static const size_t SF = (size_t)CH * HW;   // per-batch feature stride
static const size_t SS = (size_t)HW * HW;   // per-batch score stride

// ---- scratch (device globals: allocation-free) ----
__device__ float g_xn[(size_t)BATCH * CH * HW];
__device__ float g_q [(size_t)BATCH * CH * HW];
__device__ float g_k [(size_t)BATCH * CH * HW];
__device__ float g_v [(size_t)BATCH * CH * HW];
__device__ float g_o [(size_t)BATCH * CH * HW];
__device__ float g_s [(size_t)BATCH * HW * HW];

// ============================================================
// GroupNorm: one block per (batch, group). 16 ch * 4096 = 65536 elems.
// Writes g_xn directly.
// ============================================================
__global__ __launch_bounds__(256) void gn_kernel(
    const float* __restrict__ x, const float* __restrict__ gamma,
    const float* __restrict__ beta)
{
    const int bg = blockIdx.x;                 // 0..127  (b*32 + g)
    const int CPG = CH / NG;                   // 16
    const size_t base = (size_t)bg * CPG * HW;
    const int n = CPG * HW;                    // 65536
    const float4* xv = (const float4*)(x + base);
    float4* yv = (float4*)(g_xn + base);
    const int t = threadIdx.x;

    float s = 0.f, ss = 0.f;
    for (int i = t; i < n / 4; i += 256) {
        float4 v = xv[i];
        s  += v.x + v.y + v.z + v.w;
        ss += v.x*v.x + v.y*v.y + v.z*v.z + v.w*v.w;
    }
    __shared__ float sh[64];
    #pragma unroll
    for (int o = 16; o > 0; o >>= 1) {
        s  += __shfl_xor_sync(~0u, s, o);
        ss += __shfl_xor_sync(~0u, ss, o);
    }
    const int warp = t >> 5, lane = t & 31;
    if (lane == 0) { sh[warp] = s; sh[32 + warp] = ss; }
    __syncthreads();
    if (warp == 0) {
        float a = (lane < 8) ? sh[lane] : 0.f;
        float b = (lane < 8) ? sh[32 + lane] : 0.f;
        #pragma unroll
        for (int o = 4; o > 0; o >>= 1) {
            a += __shfl_xor_sync(~0u, a, o);
            b += __shfl_xor_sync(~0u, b, o);
        }
        if (lane == 0) { sh[0] = a; sh[1] = b; }
    }
    __syncthreads();
    const float mean = sh[0] / n;
    const float var  = sh[1] / n - mean * mean;
    const float inv  = rsqrtf(var + 1e-6f);
    const int gbase = (bg % NG) * CPG;

    for (int i = t; i < n / 4; i += 256) {
        int ch = i / (HW / 4);
        float ga = gamma[gbase + ch] * inv;
        float be = beta[gbase + ch];
        float4 v = xv[i];
        v.x = (v.x - mean) * ga + be;
        v.y = (v.y - mean) * ga + be;
        v.z = (v.z - mean) * ga + be;
        v.w = (v.w - mean) * ga + be;
        yv[i] = v;
    }
}

// ============================================================
// Row softmax over 4096 columns of g_s. One block (256 thr) per row.
// ============================================================
__global__ __launch_bounds__(256) void softmax_kernel()
{
    float4* pv = (float4*)(g_s + (size_t)blockIdx.x * HW);
    const int t = threadIdx.x;
    float4 v[4];
    float mx = -1e30f;
    #pragma unroll
    for (int j = 0; j < 4; j++) {
        v[j] = pv[t + 256 * j];
        mx = fmaxf(mx, fmaxf(fmaxf(v[j].x, v[j].y), fmaxf(v[j].z, v[j].w)));
    }
    __shared__ float sh[8];
    #pragma unroll
    for (int o = 16; o > 0; o >>= 1) mx = fmaxf(mx, __shfl_xor_sync(~0u, mx, o));
    if ((t & 31) == 0) sh[t >> 5] = mx;
    __syncthreads();
    const float m0 = fmaxf(fmaxf(fmaxf(sh[0], sh[1]), fmaxf(sh[2], sh[3])),
                           fmaxf(fmaxf(sh[4], sh[5]), fmaxf(sh[6], sh[7])));
    __syncthreads();
    float sum = 0.f;
    #pragma unroll
    for (int j = 0; j < 4; j++) {
        v[j].x = __expf(v[j].x - m0);
        v[j].y = __expf(v[j].y - m0);
        v[j].z = __expf(v[j].z - m0);
        v[j].w = __expf(v[j].w - m0);
        sum += v[j].x + v[j].y + v[j].z + v[j].w;
    }
    #pragma unroll
    for (int o = 16; o > 0; o >>= 1) sum += __shfl_xor_sync(~0u, sum, o);
    if ((t & 31) == 0) sh[t >> 5] = sum;
    __syncthreads();
    const float tot = sh[0]+sh[1]+sh[2]+sh[3]+sh[4]+sh[5]+sh[6]+sh[7];
    const float inv = 1.f / tot;
    #pragma unroll
    for (int j = 0; j < 4; j++) {
        v[j].x *= inv; v[j].y *= inv; v[j].z *= inv; v[j].w *= inv;
        pv[t + 256 * j] = v[j];
    }
}

// ============================================================
// Tiled SGEMM device core. C = alpha * op(A) * op(B) [+ bias[m]] [+ res]
//   TA=0: A is M x K row-major; TA=1: A is K x M row-major (A^T)
//   TB=0: B is K x N row-major; TB=1: B is N x K row-major (B^T)
// 128x128x16 tile, 256 threads, 8x8 microtile (4+4 split).
// Tile position from blockIdx.x/y; caller resolves batch pointers.
// ============================================================
template<int TA, int TB, bool HAS_BIAS, bool HAS_RES>
__device__ __forceinline__ void gemm_dev(
    const float* __restrict__ A, const float* __restrict__ B,
    const float* __restrict__ bias, const float* __restrict__ res,
    float* __restrict__ Cp,
    int K, int lda, int ldb, int ldc, float alpha)
{
    const int m0 = blockIdx.y * 128;
    const int n0 = blockIdx.x * 128;

    __shared__ float As[16][128];
    __shared__ float Bs[16][128];

    const int tid = threadIdx.x;
    const int tx = tid & 15, ty = tid >> 4;

    float acc[8][8] = {};

    for (int k0 = 0; k0 < K; k0 += 16) {
        if (TA == 0) {
            int m = tid >> 1, k8 = (tid & 1) * 8;
            const float* src = A + (size_t)(m0 + m) * lda + k0 + k8;
            #pragma unroll
            for (int u = 0; u < 8; u++) As[k8 + u][m] = src[u];
        } else {
            int k = tid >> 4, m8 = (tid & 15) * 8;
            const float* src = A + (size_t)(k0 + k) * lda + m0 + m8;
            float4 a0 = *(const float4*)(src);
            float4 a1 = *(const float4*)(src + 4);
            *(float4*)&As[k][m8]     = a0;
            *(float4*)&As[k][m8 + 4] = a1;
        }
        if (TB == 0) {
            int k = tid >> 4, n8 = (tid & 15) * 8;
            const float* src = B + (size_t)(k0 + k) * ldb + n0 + n8;
            float4 b0 = *(const float4*)(src);
            float4 b1 = *(const float4*)(src + 4);
            *(float4*)&Bs[k][n8]     = b0;
            *(float4*)&Bs[k][n8 + 4] = b1;
        } else {
            int n = tid >> 1, k8 = (tid & 1) * 8;
            const float* src = B + (size_t)(n0 + n) * ldb + k0 + k8;
            #pragma unroll
            for (int u = 0; u < 8; u++) Bs[k8 + u][n] = src[u];
        }
        __syncthreads();

        #pragma unroll
        for (int kk = 0; kk < 16; kk++) {
            float4 a0 = *(const float4*)&As[kk][ty * 4];
            float4 a1 = *(const float4*)&As[kk][64 + ty * 4];
            float4 b0 = *(const float4*)&Bs[kk][tx * 4];
            float4 b1 = *(const float4*)&Bs[kk][64 + tx * 4];
            float a[8] = {a0.x,a0.y,a0.z,a0.w,a1.x,a1.y,a1.z,a1.w};
            float b[8] = {b0.x,b0.y,b0.z,b0.w,b1.x,b1.y,b1.z,b1.w};
            #pragma unroll
            for (int i = 0; i < 8; i++)
                #pragma unroll
                for (int j = 0; j < 8; j++)
                    acc[i][j] += a[i] * b[j];
        }
        __syncthreads();
    }

    #pragma unroll
    for (int i = 0; i < 8; i++) {
        int r = m0 + ((i < 4) ? (ty * 4 + i) : (64 + ty * 4 + i - 4));
        float bvv = HAS_BIAS ? bias[r] : 0.f;
        #pragma unroll
        for (int jj = 0; jj < 2; jj++) {
            int c0 = n0 + (jj ? (64 + tx * 4) : (tx * 4));
            float4 o;
            o.x = acc[i][jj * 4 + 0] * alpha + bvv;
            o.y = acc[i][jj * 4 + 1] * alpha + bvv;
            o.z = acc[i][jj * 4 + 2] * alpha + bvv;
            o.w = acc[i][jj * 4 + 3] * alpha + bvv;
            if (HAS_RES) {
                float4 rv = *(const float4*)&res[(size_t)r * ldc + c0];
                o.x += rv.x; o.y += rv.y; o.z += rv.z; o.w += rv.w;
            }
            *(float4*)&Cp[(size_t)r * ldc + c0] = o;
        }
    }
}

// ---- wrapper kernels: all scratch via device globals, no host symbols ----

// QKV fused: z = b*3 + p, p in {0=q, 1=k, 2=v}
__global__ __launch_bounds__(256) void qkv_kernel(
    const float* __restrict__ wq, const float* __restrict__ bq,
    const float* __restrict__ wk, const float* __restrict__ bk,
    const float* __restrict__ wv, const float* __restrict__ bv)
{
    const int b = blockIdx.z / 3, p = blockIdx.z % 3;
    const float* W    = (p == 0) ? wq : (p == 1) ? wk : wv;
    const float* bias = (p == 0) ? bq : (p == 1) ? bk : bv;
    float* dst = ((p == 0) ? g_q : (p == 1) ? g_k : g_v) + (size_t)b * CH * HW;
    gemm_dev<0,0,true,false>(W, g_xn + (size_t)b * CH * HW, bias, nullptr, dst,
                             CH, CH, HW, HW, 1.f);
}

// S = alpha * Q^T K  (TN)
__global__ __launch_bounds__(256) void score_kernel()
{
    const int b = blockIdx.z;
    gemm_dev<1,0,false,false>(g_q + (size_t)b * CH * HW, g_k + (size_t)b * CH * HW,
                              nullptr, nullptr, g_s + (size_t)b * HW * HW,
                              CH, HW, HW, HW, 0.044194173824159216f);
}

// O1 = V @ P^T  (NT)
__global__ __launch_bounds__(256) void av_kernel()
{
    const int b = blockIdx.z;
    gemm_dev<0,1,false,false>(g_v + (size_t)b * CH * HW, g_s + (size_t)b * HW * HW,
                              nullptr, nullptr, g_o + (size_t)b * CH * HW,
                              HW, HW, HW, HW, 1.f);
}

// out = Wo @ O1 + bo + x
__global__ __launch_bounds__(256) void out_kernel(
    const float* __restrict__ wo, const float* __restrict__ bo,
    const float* __restrict__ x, float* __restrict__ out)
{
    const int b = blockIdx.z;
    gemm_dev<0,0,true,true>(wo, g_o + (size_t)b * CH * HW, bo,
                            x + (size_t)b * CH * HW, out + (size_t)b * CH * HW,
                            CH, CH, HW, HW, 1.f);
}

// ============================================================
extern "C" void kernel_launch(void* const* d_in, const int* in_sizes, int n_in,
                              void* d_out, int out_size)
{
    const float* x   = (const float*)d_in[0];
    const float* gnw = (const float*)d_in[1];
    const float* gnb = (const float*)d_in[2];
    const float* wq  = (const float*)d_in[3];
    const float* bq  = (const float*)d_in[4];
    const float* wk  = (const float*)d_in[5];
    const float* bk  = (const float*)d_in[6];
    const float* wv  = (const float*)d_in[7];
    const float* bv  = (const float*)d_in[8];
    const float* wo  = (const float*)d_in[9];
    const float* bo  = (const float*)d_in[10];
    float* out = (float*)d_out;

    gn_kernel<<<BATCH * NG, 256>>>(x, gnw, gnb);

    dim3 gQKV(HW / 128, CH / 128, BATCH * 3);   // (32, 4, 12)
    qkv_kernel<<<gQKV, 256>>>(wq, bq, wk, bk, wv, bv);

    dim3 gS(HW / 128, HW / 128, BATCH);         // (32, 32, 4)
    score_kernel<<<gS, 256>>>();

    softmax_kernel<<<BATCH * HW, 256>>>();

    dim3 gF(HW / 128, CH / 128, BATCH);         // (32, 4, 4)
    av_kernel<<<gF, 256>>>();

    out_kernel<<<gF, 256>>>(wo, bo, x, out);
}

// round 6
// speedup vs baseline: 2.3791x; 2.3791x over previous
#include <cuda_runtime.h>
#include <cuda_bf16.h>
#include <cstdint>
#include <math.h>

#define BATCH 4
#define CH    512
#define HW    4096
#define NG    32

static const size_t SFE = (size_t)CH * HW;

// ================= scratch (device globals) =================
__device__ float g_xn[(size_t)BATCH * CH * HW];
__device__ float g_s [(size_t)BATCH * HW * HW];

__device__ __nv_bfloat16 g_xnT_h[(size_t)BATCH * HW * CH];
__device__ __nv_bfloat16 g_xnT_l[(size_t)BATCH * HW * CH];
__device__ __nv_bfloat16 g_qT_h [(size_t)BATCH * HW * CH];
__device__ __nv_bfloat16 g_qT_l [(size_t)BATCH * HW * CH];
__device__ __nv_bfloat16 g_kT_h [(size_t)BATCH * HW * CH];
__device__ __nv_bfloat16 g_kT_l [(size_t)BATCH * HW * CH];
__device__ __nv_bfloat16 g_v_h  [(size_t)BATCH * CH * HW];
__device__ __nv_bfloat16 g_v_l  [(size_t)BATCH * CH * HW];
__device__ __nv_bfloat16 g_ot_h [(size_t)BATCH * HW * CH];
__device__ __nv_bfloat16 g_ot_l [(size_t)BATCH * HW * CH];
__device__ __nv_bfloat16 g_P_h  [(size_t)BATCH * HW * HW];
__device__ __nv_bfloat16 g_P_l  [(size_t)BATCH * HW * HW];
__device__ __nv_bfloat16 g_w_h  [(size_t)4 * CH * CH];
__device__ __nv_bfloat16 g_w_l  [(size_t)4 * CH * CH];

// ================= helpers =================
__device__ __forceinline__ uint32_t smem_u32(const void* p) {
    uint32_t a;
    asm("{ .reg .u64 t; cvta.to.shared.u64 t, %1; cvt.u32.u64 %0, t; }"
        : "=r"(a) : "l"(p));
    return a;
}
__device__ __forceinline__ uint32_t pack2(__nv_bfloat16 a, __nv_bfloat16 b) {
    return (uint32_t)__bfloat16_as_ushort(a) |
           ((uint32_t)__bfloat16_as_ushort(b) << 16);
}
__device__ __forceinline__ void split(float v, __nv_bfloat16& h, __nv_bfloat16& l) {
    h = __float2bfloat16(v);
    l = __float2bfloat16(v - __bfloat162float(h));
}

#define LDS32(r, a) asm volatile("ld.shared.b32 %0, [%1];" : "=r"(r) : "r"(a))

__device__ __forceinline__ void mma16816(float* d, const uint32_t* a,
                                         const uint32_t* b) {
    asm volatile(
        "mma.sync.aligned.m16n8k16.row.col.f32.bf16.bf16.f32 "
        "{%0,%1,%2,%3}, {%4,%5,%6,%7}, {%8,%9}, {%0,%1,%2,%3};"
        : "+f"(d[0]), "+f"(d[1]), "+f"(d[2]), "+f"(d[3])
        : "r"(a[0]), "r"(a[1]), "r"(a[2]), "r"(a[3]), "r"(b[0]), "r"(b[1]));
}

// smem: 4 matrices (Ah, Al, Bh, Bl), 128 rows x 32 bf16, padded to 80B rows.
// per-mat 10240 B, per-stage 40960 B, 2 stages = 81920 B.
#define ROWB   80
#define MATB   10240
#define STAGEB 40960
#define SM_BYTES (2 * STAGEB)

// ============================================================
// split-bf16 GEMM via mma.sync.  Ctile(128x128) = A(MxK) . B(NxK)^T
// A, B K-major bf16 hi/lo.  K multiple of 32.
// ============================================================
template<bool SPLIT, bool BROW, bool BCOL, bool RES>
__device__ __forceinline__ void tgemm(
    const __nv_bfloat16* __restrict__ Ah, const __nv_bfloat16* __restrict__ Al, int lda,
    const __nv_bfloat16* __restrict__ Bh, const __nv_bfloat16* __restrict__ Bl, int ldb,
    int K, float alpha,
    const float* __restrict__ bias_row, const float* __restrict__ bias_col,
    const float* __restrict__ res, int ldr,
    float* __restrict__ Cf, __nv_bfloat16* __restrict__ Chi,
    __nv_bfloat16* __restrict__ Clo, int ldc)
{
    extern __shared__ char smem[];
    const uint32_t sb = smem_u32(smem);
    const int tid  = threadIdx.x;
    const int wid  = tid >> 5, lane = tid & 31;
    const int mw   = wid >> 1, nw = wid & 1;         // warp tile: 32m x 64n
    const int m0   = blockIdx.y * 128, n0 = blockIdx.x * 128;
    const int C    = K >> 5;                          // 32-wide k chunks

    float acc[2][8][4];
    #pragma unroll
    for (int i = 0; i < 2; i++)
        #pragma unroll
        for (int j = 0; j < 8; j++)
            #pragma unroll
            for (int q = 0; q < 4; q++) acc[i][j][q] = 0.f;

    // ---- async loader for chunk ck into stage (ck&1) ----
    auto load_chunk = [&](int ck) {
        const uint32_t stage = sb + (ck & 1) * STAGEB;
        #pragma unroll
        for (int i = 0; i < 8; i++) {
            const int unit = tid + 256 * i;          // 2048 units of 16B
            const int mat = unit >> 9;
            const int row = (unit >> 2) & 127;
            const int u   = unit & 3;
            const __nv_bfloat16* src =
                (mat == 0) ? Ah : (mat == 1) ? Al : (mat == 2) ? Bh : Bl;
            const int ld_ = (mat < 2) ? lda : ldb;
            const int r0  = (mat < 2) ? m0  : n0;
            const char* gsrc =
                (const char*)(src + (size_t)(r0 + row) * ld_ + ck * 32) + u * 16;
            const uint32_t dst = stage + mat * MATB + row * ROWB + u * 16;
            asm volatile("cp.async.cg.shared.global [%0], [%1], 16;"
                         :: "r"(dst), "l"(gsrc));
        }
        asm volatile("cp.async.commit_group;" ::: "memory");
    };

    load_chunk(0);

    const int gq = lane >> 2, qt = lane & 3;          // groupID, threadID_in_group

    for (int c = 0; c < C; c++) {
        if (c + 1 < C) load_chunk(c + 1);
        if (c + 1 < C) asm volatile("cp.async.wait_group 1;" ::: "memory");
        else           asm volatile("cp.async.wait_group 0;" ::: "memory");
        __syncthreads();

        const uint32_t stage = sb + (c & 1) * STAGEB;
        const uint32_t aB = stage + (mw * 32 + gq) * ROWB + qt * 4;
        const uint32_t bB = stage + 2 * MATB + (nw * 64 + gq) * ROWB + qt * 4;

        #pragma unroll
        for (int ks = 0; ks < 2; ks++) {
            const uint32_t ko = ks * 32;              // 16 elems = 32 B
            uint32_t ah[2][4], al[2][4];
            #pragma unroll
            for (int mt = 0; mt < 2; mt++) {
                const uint32_t a0 = aB + mt * 16 * ROWB + ko;
                LDS32(ah[mt][0], a0);
                LDS32(ah[mt][1], a0 + 8 * ROWB);
                LDS32(ah[mt][2], a0 + 16);
                LDS32(ah[mt][3], a0 + 8 * ROWB + 16);
                const uint32_t a1 = a0 + MATB;
                LDS32(al[mt][0], a1);
                LDS32(al[mt][1], a1 + 8 * ROWB);
                LDS32(al[mt][2], a1 + 16);
                LDS32(al[mt][3], a1 + 8 * ROWB + 16);
            }
            #pragma unroll
            for (int nt = 0; nt < 8; nt++) {
                uint32_t bh[2], bl[2];
                const uint32_t b0 = bB + nt * 8 * ROWB + ko;
                LDS32(bh[0], b0);
                LDS32(bh[1], b0 + 16);
                LDS32(bl[0], b0 + MATB);
                LDS32(bl[1], b0 + MATB + 16);
                #pragma unroll
                for (int mt = 0; mt < 2; mt++) {
                    mma16816(acc[mt][nt], ah[mt], bh);
                    mma16816(acc[mt][nt], ah[mt], bl);
                    mma16816(acc[mt][nt], al[mt], bh);
                }
            }
        }
        __syncthreads();
    }

    // ---- epilogue ----
    #pragma unroll
    for (int mt = 0; mt < 2; mt++) {
        const int mA = m0 + mw * 32 + mt * 16 + gq;   // rows mA, mA+8
        #pragma unroll
        for (int half = 0; half < 2; half++) {
            const int m = mA + half * 8;
            const float br = BROW ? bias_row[m] : 0.f;
            #pragma unroll
            for (int nt = 0; nt < 8; nt++) {
                const int n = n0 + nw * 64 + nt * 8 + qt * 2;
                float vx = acc[mt][nt][half * 2 + 0] * alpha + br;
                float vy = acc[mt][nt][half * 2 + 1] * alpha + br;
                if (BCOL) { vx += bias_col[n]; vy += bias_col[n + 1]; }
                if (RES) {
                    const float* rp = res + (size_t)m * ldr + n;
                    vx += rp[0]; vy += rp[1];
                }
                if (SPLIT) {
                    __nv_bfloat16 h0, h1, l0, l1;
                    split(vx, h0, l0); split(vy, h1, l1);
                    *(uint32_t*)(Chi + (size_t)m * ldc + n) = pack2(h0, h1);
                    *(uint32_t*)(Clo + (size_t)m * ldc + n) = pack2(l0, l1);
                } else {
                    float2 o = {vx, vy};
                    *(float2*)(Cf + (size_t)m * ldc + n) = o;
                }
            }
        }
    }
}

// ================= wrapper kernels =================

__global__ __launch_bounds__(256, 1) void tg_qk(
    const float* __restrict__ bq, const float* __restrict__ bk)
{
    const int b = blockIdx.z >> 1, s = blockIdx.z & 1;
    const __nv_bfloat16* Wh = g_w_h + (size_t)s * CH * CH;
    const __nv_bfloat16* Wl = g_w_l + (size_t)s * CH * CH;
    __nv_bfloat16* Ch = (s == 0 ? g_qT_h : g_kT_h) + (size_t)b * HW * CH;
    __nv_bfloat16* Cl = (s == 0 ? g_qT_l : g_kT_l) + (size_t)b * HW * CH;
    tgemm<true, false, true, false>(
        g_xnT_h + (size_t)b * HW * CH, g_xnT_l + (size_t)b * HW * CH, CH,
        Wh, Wl, CH, CH, 1.f, nullptr, (s == 0 ? bq : bk), nullptr, 0,
        nullptr, Ch, Cl, CH);
}

__global__ __launch_bounds__(256, 1) void tg_v(const float* __restrict__ bv)
{
    const int b = blockIdx.z;
    tgemm<true, true, false, false>(
        g_w_h + (size_t)2 * CH * CH, g_w_l + (size_t)2 * CH * CH, CH,
        g_xnT_h + (size_t)b * HW * CH, g_xnT_l + (size_t)b * HW * CH, CH,
        CH, 1.f, bv, nullptr, nullptr, 0,
        nullptr, g_v_h + (size_t)b * CH * HW, g_v_l + (size_t)b * CH * HW, HW);
}

__global__ __launch_bounds__(256, 1) void tg_score()
{
    const int b = blockIdx.z;
    tgemm<false, false, false, false>(
        g_qT_h + (size_t)b * HW * CH, g_qT_l + (size_t)b * HW * CH, CH,
        g_kT_h + (size_t)b * HW * CH, g_kT_l + (size_t)b * HW * CH, CH,
        CH, 0.044194173824159216f, nullptr, nullptr, nullptr, 0,
        g_s + (size_t)b * HW * HW, nullptr, nullptr, HW);
}

__global__ __launch_bounds__(256, 1) void tg_av()
{
    const int b = blockIdx.z;
    tgemm<true, false, false, false>(
        g_P_h + (size_t)b * HW * HW, g_P_l + (size_t)b * HW * HW, HW,
        g_v_h + (size_t)b * CH * HW, g_v_l + (size_t)b * CH * HW, HW,
        HW, 1.f, nullptr, nullptr, nullptr, 0,
        nullptr, g_ot_h + (size_t)b * HW * CH, g_ot_l + (size_t)b * HW * CH, CH);
}

__global__ __launch_bounds__(256, 1) void tg_out(
    const float* __restrict__ bo, const float* __restrict__ x,
    float* __restrict__ out)
{
    const int b = blockIdx.z;
    tgemm<false, true, false, true>(
        g_w_h + (size_t)3 * CH * CH, g_w_l + (size_t)3 * CH * CH, CH,
        g_ot_h + (size_t)b * HW * CH, g_ot_l + (size_t)b * HW * CH, CH,
        CH, 1.f, bo, nullptr, x + (size_t)b * SFE, HW,
        out + (size_t)b * SFE, nullptr, nullptr, HW);
}

// ================= GroupNorm =================
__global__ __launch_bounds__(256) void gn_kernel(
    const float* __restrict__ x, const float* __restrict__ gamma,
    const float* __restrict__ beta)
{
    const int bg = blockIdx.x;
    const int CPG = CH / NG;
    const size_t base = (size_t)bg * CPG * HW;
    const int n = CPG * HW;
    const float4* xv = (const float4*)(x + base);
    float4* yv = (float4*)(g_xn + base);
    const int t = threadIdx.x;

    float s = 0.f, ss = 0.f;
    for (int i = t; i < n / 4; i += 256) {
        float4 v = xv[i];
        s  += v.x + v.y + v.z + v.w;
        ss += v.x*v.x + v.y*v.y + v.z*v.z + v.w*v.w;
    }
    __shared__ float sh[64];
    #pragma unroll
    for (int o = 16; o > 0; o >>= 1) {
        s  += __shfl_xor_sync(~0u, s, o);
        ss += __shfl_xor_sync(~0u, ss, o);
    }
    const int warp = t >> 5, lane = t & 31;
    if (lane == 0) { sh[warp] = s; sh[32 + warp] = ss; }
    __syncthreads();
    if (warp == 0) {
        float a = (lane < 8) ? sh[lane] : 0.f;
        float b = (lane < 8) ? sh[32 + lane] : 0.f;
        #pragma unroll
        for (int o = 4; o > 0; o >>= 1) {
            a += __shfl_xor_sync(~0u, a, o);
            b += __shfl_xor_sync(~0u, b, o);
        }
        if (lane == 0) { sh[0] = a; sh[1] = b; }
    }
    __syncthreads();
    const float mean = sh[0] / n;
    const float var  = sh[1] / n - mean * mean;
    const float inv  = rsqrtf(var + 1e-6f);
    const int gbase = (bg % NG) * CPG;

    for (int i = t; i < n / 4; i += 256) {
        int ch = i / (HW / 4);
        float ga = gamma[gbase + ch] * inv;
        float be = beta[gbase + ch];
        float4 v = xv[i];
        v.x = (v.x - mean) * ga + be;
        v.y = (v.y - mean) * ga + be;
        v.z = (v.z - mean) * ga + be;
        v.w = (v.w - mean) * ga + be;
        yv[i] = v;
    }
}

// ================= transpose + split =================
__global__ __launch_bounds__(256) void xpose_kernel()
{
    __shared__ float t[32][33];
    const int b = blockIdx.z;
    const int i0 = blockIdx.x * 32, c0 = blockIdx.y * 32;
    const int tx = threadIdx.x & 31, ty = threadIdx.x >> 5;
    const float* src = g_xn + (size_t)b * SFE;
    #pragma unroll
    for (int j = 0; j < 4; j++)
        t[ty + 8*j][tx] = src[(size_t)(c0 + ty + 8*j) * HW + i0 + tx];
    __syncthreads();
    #pragma unroll
    for (int j = 0; j < 4; j++) {
        float v = t[tx][ty + 8*j];
        __nv_bfloat16 h, l; split(v, h, l);
        size_t d = (size_t)b * HW * CH + (size_t)(i0 + ty + 8*j) * CH + c0 + tx;
        g_xnT_h[d] = h; g_xnT_l[d] = l;
    }
}

// ================= weight split =================
__global__ __launch_bounds__(256) void wconv_kernel(
    const float* __restrict__ wq, const float* __restrict__ wk,
    const float* __restrict__ wv, const float* __restrict__ wo)
{
    const size_t idx = (size_t)blockIdx.x * 256 + threadIdx.x;
    const int which = (int)(idx >> 18);
    const size_t off = idx & ((1 << 18) - 1);
    const float* w = (which == 0) ? wq : (which == 1) ? wk : (which == 2) ? wv : wo;
    __nv_bfloat16 h, l; split(w[off], h, l);
    g_w_h[idx] = h; g_w_l[idx] = l;
}

// ================= softmax -> P hi/lo =================
__global__ __launch_bounds__(256) void softmax_kernel()
{
    const size_t row = blockIdx.x;
    const float4* pv = (const float4*)(g_s + row * HW);
    __nv_bfloat16* ph = g_P_h + row * HW;
    __nv_bfloat16* pl = g_P_l + row * HW;
    const int t = threadIdx.x;
    float4 v[4];
    float mx = -1e30f;
    #pragma unroll
    for (int j = 0; j < 4; j++) {
        v[j] = pv[t + 256 * j];
        mx = fmaxf(mx, fmaxf(fmaxf(v[j].x, v[j].y), fmaxf(v[j].z, v[j].w)));
    }
    __shared__ float sh[8];
    #pragma unroll
    for (int o = 16; o > 0; o >>= 1) mx = fmaxf(mx, __shfl_xor_sync(~0u, mx, o));
    if ((t & 31) == 0) sh[t >> 5] = mx;
    __syncthreads();
    const float m0 = fmaxf(fmaxf(fmaxf(sh[0], sh[1]), fmaxf(sh[2], sh[3])),
                           fmaxf(fmaxf(sh[4], sh[5]), fmaxf(sh[6], sh[7])));
    __syncthreads();
    float sum = 0.f;
    #pragma unroll
    for (int j = 0; j < 4; j++) {
        v[j].x = __expf(v[j].x - m0);
        v[j].y = __expf(v[j].y - m0);
        v[j].z = __expf(v[j].z - m0);
        v[j].w = __expf(v[j].w - m0);
        sum += v[j].x + v[j].y + v[j].z + v[j].w;
    }
    #pragma unroll
    for (int o = 16; o > 0; o >>= 1) sum += __shfl_xor_sync(~0u, sum, o);
    if ((t & 31) == 0) sh[t >> 5] = sum;
    __syncthreads();
    const float tot = sh[0]+sh[1]+sh[2]+sh[3]+sh[4]+sh[5]+sh[6]+sh[7];
    const float inv = 1.f / tot;
    #pragma unroll
    for (int j = 0; j < 4; j++) {
        float4 e = v[j];
        e.x *= inv; e.y *= inv; e.z *= inv; e.w *= inv;
        __nv_bfloat16 h0,h1,h2,h3,l0,l1,l2,l3;
        split(e.x,h0,l0); split(e.y,h1,l1); split(e.z,h2,l2); split(e.w,h3,l3);
        const int eo = (t + 256 * j) * 4;
        uint2 hv = { pack2(h0,h1), pack2(h2,h3) };
        uint2 lv = { pack2(l0,l1), pack2(l2,l3) };
        *(uint2*)(ph + eo) = hv;
        *(uint2*)(pl + eo) = lv;
    }
}

// ============================================================
extern "C" void kernel_launch(void* const* d_in, const int* in_sizes, int n_in,
                              void* d_out, int out_size)
{
    const float* x   = (const float*)d_in[0];
    const float* gnw = (const float*)d_in[1];
    const float* gnb = (const float*)d_in[2];
    const float* wq  = (const float*)d_in[3];
    const float* bq  = (const float*)d_in[4];
    const float* wk  = (const float*)d_in[5];
    const float* bk  = (const float*)d_in[6];
    const float* wv  = (const float*)d_in[7];
    const float* bv  = (const float*)d_in[8];
    const float* wo  = (const float*)d_in[9];
    const float* bo  = (const float*)d_in[10];
    float* out = (float*)d_out;

    cudaFuncSetAttribute(tg_qk,    cudaFuncAttributeMaxDynamicSharedMemorySize, SM_BYTES);
    cudaFuncSetAttribute(tg_v,     cudaFuncAttributeMaxDynamicSharedMemorySize, SM_BYTES);
    cudaFuncSetAttribute(tg_score, cudaFuncAttributeMaxDynamicSharedMemorySize, SM_BYTES);
    cudaFuncSetAttribute(tg_av,    cudaFuncAttributeMaxDynamicSharedMemorySize, SM_BYTES);
    cudaFuncSetAttribute(tg_out,   cudaFuncAttributeMaxDynamicSharedMemorySize, SM_BYTES);

    gn_kernel<<<BATCH * NG, 256>>>(x, gnw, gnb);

    dim3 gx(HW / 32, CH / 32, BATCH);
    xpose_kernel<<<gx, 256>>>();

    wconv_kernel<<<4 * CH * CH / 256, 256>>>(wq, wk, wv, wo);

    dim3 gqk(CH / 128, HW / 128, BATCH * 2);
    tg_qk<<<gqk, 256, SM_BYTES>>>(bq, bk);

    dim3 gv(HW / 128, CH / 128, BATCH);
    tg_v<<<gv, 256, SM_BYTES>>>(bv);

    dim3 gs(HW / 128, HW / 128, BATCH);
    tg_score<<<gs, 256, SM_BYTES>>>();

    softmax_kernel<<<BATCH * HW, 256>>>();

    dim3 ga(CH / 128, HW / 128, BATCH);
    tg_av<<<ga, 256, SM_BYTES>>>();

    dim3 go(HW / 128, CH / 128, BATCH);
    tg_out<<<go, 256, SM_BYTES>>>(bo, x, out);
}